// round 16
// baseline (speedup 1.0000x reference)
#include <cuda_runtime.h>
#include <math.h>

typedef unsigned long long ull;

// Shapes
#define NSEQ_C 8192            // B*W
#define T_CH   48              // chars per word
#define M_C    (NSEQ_C*T_CH)   // 393216 char rows
#define M_M    8192            // msg-level rows (B*W)

// ---------------- static device scratch (no allocations allowed) ----------------
__device__ float g_xg[301989888ull];        // [2][M][384] gate preacts
__device__ float g_out[100663296ull];       // [M][256] BiGRU outputs
__device__ float g_words[2097152ull];       // [8192][256] pooled word vectors / messages

// ---------------- helpers ----------------
__device__ __forceinline__ void ffma2(ull &d, ull a, ull b) {
    asm("fma.rn.f32x2 %0, %1, %2, %0;" : "+l"(d) : "l"(a), "l"(b));
}
__device__ __forceinline__ float f2sum(ull v) {
    unsigned lo, hi;
    asm("mov.b64 {%0,%1}, %2;" : "=r"(lo), "=r"(hi) : "l"(v));
    return __uint_as_float(lo) + __uint_as_float(hi);
}
__device__ __forceinline__ float sigmoidf_(float x) { return 1.0f / (1.0f + expf(-x)); }

// Load NU*4 floats of a weight row into packed-f32x2 registers (16B loads).
template <int NU>
__device__ __forceinline__ void loadW(ull* w2, const float* __restrict__ W) {
    const ulonglong2* wr = (const ulonglong2*)W;
#pragma unroll
    for (int j = 0; j < NU; j++) { ulonglong2 v = wr[j]; w2[2 * j] = v.x; w2[2 * j + 1] = v.y; }
}

// Single dot over NU*4 floats (4 independent chains) — R10 version.
template <int NU>
__device__ __forceinline__ float dotT(const ull* w2, const float* xp) {
    const ulonglong2* xr = (const ulonglong2*)xp;
    ull a0 = 0, a1 = 0, a2 = 0, a3 = 0;
#pragma unroll
    for (int j = 0; j < NU; j += 2) {
        ulonglong2 v0 = xr[j];
        ulonglong2 v1 = xr[j + 1];
        ffma2(a0, w2[2 * j],     v0.x);
        ffma2(a1, w2[2 * j + 1], v0.y);
        ffma2(a2, w2[2 * j + 2], v1.x);
        ffma2(a3, w2[2 * j + 3], v1.y);
    }
    return (f2sum(a0) + f2sum(a1)) + (f2sum(a2) + f2sum(a3));
}

// C simultaneous dots, two independent chains per column.
template <int C, int NU>
__device__ __forceinline__ void dotC(const ull* w, const float* xp, float* o) {
    const ulonglong2* xr = (const ulonglong2*)xp;
    ull ax[C], ay[C];
#pragma unroll
    for (int c = 0; c < C; c++) { ax[c] = 0; ay[c] = 0; }
#pragma unroll
    for (int j = 0; j < NU; j++) {
        ulonglong2 v = xr[j];
#pragma unroll
        for (int c = 0; c < C; c++) {
            ffma2(ax[c], w[c * 2 * NU + 2 * j],     v.x);
            ffma2(ay[c], w[c * 2 * NU + 2 * j + 1], v.y);
        }
    }
#pragma unroll
    for (int c = 0; c < C; c++) o[c] = f2sum(ax[c]) + f2sum(ay[c]);
}

// ---------------- K1: char input gates, fused embedding gather (K=64) ----------------
// 384 thr, one dir per block. slot = 0..191 (cols slot, slot+192: C=2),
// kh = tid>=192 (warp-uniform half-K). 64 weight regs, 4 FFMA2 per LDS.128.
__global__ __launch_bounds__(384, 1)
void xg_char_kernel(const int* __restrict__ chars, const float* __restrict__ emb,
                    const float* __restrict__ WihF, const float* __restrict__ WihB,
                    const float* __restrict__ biF,  const float* __restrict__ biB)
{
    const int RB = 96, RCH = 16;
    extern __shared__ __align__(16) float sh[];
    float* xs = sh;                  // [96][64]
    float* ps = xs + RB * 64;        // [16][2*384]
    float* sb = ps + RCH * 768;      // [384]

    const int dir = blockIdx.x;
    const int m0  = blockIdx.y * RB;
    const int tid = threadIdx.x;
    const int kh  = tid >= 192;         // warp-uniform (6 warps each)
    const int slot = kh ? (tid - 192) : tid;   // 0..191

    const float* W = dir ? WihB : WihF;
    ull w[2 * 16];                      // 2 cols x 32 floats -> 32 ull = 64 regs (FIXED SIZE)
    loadW<8>(w,      W + (size_t)slot * 64 + kh * 32);
    loadW<8>(w + 16, W + (size_t)(slot + 192) * 64 + kh * 32);
    if (tid < 384) sb[tid] = (dir ? biB : biF)[tid];

    float4* xs4 = (float4*)xs;
    const float4* emb4 = (const float4*)emb;
    for (int idx = tid; idx < RB * 16; idx += 384) {
        int r = idx >> 4, q = idx & 15;
        int ch = chars[m0 + r];
        xs4[idx] = emb4[(size_t)ch * 16 + q];
    }
    __syncthreads();

    float* outp = g_xg + (size_t)dir * M_C * 384 + (size_t)m0 * 384;
    for (int chk = 0; chk < RB / RCH; chk++) {
        int r0 = chk * RCH;
#pragma unroll 2
        for (int rl = 0; rl < RCH; rl++) {
            float o[2];
            dotC<2, 8>(w, xs + (r0 + rl) * 64 + kh * 32, o);
            ps[rl * 768 + kh * 384 + slot]       = o[0];
            ps[rl * 768 + kh * 384 + slot + 192] = o[1];
        }
        __syncthreads();
        // write: thread = column tid, loop rows (coalesced STG)
        float bias = sb[tid];
#pragma unroll 4
        for (int rl = 0; rl < RCH; rl++) {
            float v = ps[rl * 768 + tid] + ps[rl * 768 + 384 + tid] + bias;
            outp[(size_t)(r0 + rl) * 384 + tid] = v;
        }
        __syncthreads();
    }
}

// ---------------- K4: message input gates GEMM (K=256) — R14 measured-best ----------------
__global__ __launch_bounds__(256, 2)
void xg_k256_kernel(const float* __restrict__ WihF, const float* __restrict__ WihB,
                    const float* __restrict__ biF,  const float* __restrict__ biB)
{
    const int RB = 16;
    extern __shared__ __align__(16) float sh[];
    float* xs = sh;                 // [16][256]
    float* ps = xs + RB * 256;      // [16][8*64]
    float* sb = ps + RB * 512;      // [64]

    const int colg = blockIdx.x;    // 0..11
    const int m0   = blockIdx.y * RB;
    const int tid  = threadIdx.x;
    const int kq = tid >> 5, cl = tid & 31;

    ull w[2 * 16];
#pragma unroll
    for (int ci = 0; ci < 2; ci++) {
        int gcol = colg * 64 + cl + 32 * ci;
        int d = gcol >= 384, rw = gcol - d * 384;
        loadW<8>(w + ci * 16, (d ? WihB : WihF) + (size_t)rw * 256 + kq * 32);
    }
    if (tid < 64) {
        int gcol = colg * 64 + tid;
        int d = gcol >= 384, rw = gcol - d * 384;
        sb[tid] = (d ? biB : biF)[rw];
    }

    float4* xs4 = (float4*)xs;
    const float4* X4 = (const float4*)(g_words + (size_t)m0 * 256);
    for (int i = tid; i < RB * 64; i += 256) xs4[i] = X4[i];
    __syncthreads();

#pragma unroll 2
    for (int r = 0; r < RB; r++) {
        float o[2];
        dotC<2, 8>(w, xs + r * 256 + kq * 32, o);
        ps[r * 512 + kq * 64 + cl]      = o[0];
        ps[r * 512 + kq * 64 + cl + 32] = o[1];
    }
    __syncthreads();

#pragma unroll
    for (int p = 0; p < 4; p++) {
        int i = tid + p * 256;
        int r = i >> 6, col = i & 63;
        float v = sb[col];
#pragma unroll
        for (int q = 0; q < 8; q++) v += ps[r * 512 + q * 64 + col];
        int gcol = colg * 64 + col;
        int d = gcol >= 384, rw = gcol - d * 384;
        g_xg[(size_t)d * M_M * 384 + (size_t)(m0 + r) * 384 + rw] = v;
    }
}

// ---------------- K2/K5: persistent BiGRU recurrence — R10 measured-best ----------------
template <int NB>
__global__ __launch_bounds__(768, 1)
void gru_kernel(const float* __restrict__ WhF, const float* __restrict__ WhB,
                const float* __restrict__ bhF, const float* __restrict__ bhB,
                const int* __restrict__ lens, int nSeq, int T)
{
    extern __shared__ __align__(16) float sh[];
    float* hs   = sh;                         // [NB*128]
    float* HG   = hs + NB * 128;              // [384*(NB+1)]
    float* XN   = HG + 384 * (NB + 1);        // [128*(NB+1)]
    float* ps   = XN + 128 * (NB + 1);        // [NB*768]
    float* sbias= ps + NB * 768;              // [384]
    __shared__ int slen[NB];

    const int dir  = blockIdx.x;
    const int seq0 = blockIdx.y * NB;
    const int tid  = threadIdx.x;
    const int g    = tid % 384;
    const int kh   = tid / 384;               // warp-uniform (384 = 12 warps)

    const float* W = dir ? WhB : WhF;
    ull w2[32];
    loadW<16>(w2, W + (size_t)g * 128 + kh * 64);

    for (int i = tid; i < NB * 128; i += 768) hs[i] = 0.f;
    if (tid < 384) sbias[tid] = (dir ? bhB : bhF)[tid];
    if (tid < NB) slen[tid] = lens ? lens[seq0 + tid] : T;
    const float* xgD = g_xg + (size_t)dir * nSeq * T * 384;
    __syncthreads();

    const int k   = tid & 127;   // phase-2 mapping
    const int sub = tid >> 7;    // 0..5

    for (int t = 0; t < T; t++) {
        // phase 1a: half-dot partials for all b
#pragma unroll 1
        for (int b = 0; b < NB; b++)
            ps[b * 768 + tid] = dotT<16>(w2, hs + b * 128 + kh * 64);
        __syncthreads();
        // phase 1b: combine halves + bias + xg
        for (int i = tid; i < NB * 384; i += 768) {
            int b = i / 384, gg = i % 384;
            float hgv = ps[b * 768 + gg] + ps[b * 768 + gg + 384] + sbias[gg];
            int lb = slen[b];
            int it = dir ? ((t < lb) ? (lb - 1 - t) : t) : t;
            float xv = xgD[((size_t)(seq0 + b) * T + it) * 384 + gg];
            if (gg < 256) HG[gg * (NB + 1) + b] = xv + hgv;
            else { HG[gg * (NB + 1) + b] = hgv; XN[(gg - 256) * (NB + 1) + b] = xv; }
        }
        __syncthreads();
        // phase 2: gates + state update + output (6-way b split)
#pragma unroll 1
        for (int b = sub; b < NB; b += 6) {
            int lb = slen[b];
            bool valid = t < lb;
            float r = sigmoidf_(HG[k * (NB + 1) + b]);
            float z = sigmoidf_(HG[(k + 128) * (NB + 1) + b]);
            float n = tanhf(XN[k * (NB + 1) + b] + r * HG[(k + 256) * (NB + 1) + b]);
            float h = hs[b * 128 + k];
            float hnew = valid ? ((1.f - z) * n + z * h) : h;
            hs[b * 128 + k] = hnew;
            int ot = dir ? (valid ? (lb - 1 - t) : t) : t;
            size_t m = (size_t)(seq0 + b) * T + ot;
            g_out[m * 256 + (size_t)dir * 128 + k] = valid ? hnew : 0.f;
        }
        __syncthreads();
    }
}

// ---------------- K3/K6: attention pooling — R10 measured-best ----------------
template <int T>
__global__ __launch_bounds__(256, 1)
void attn_kernel(const float* __restrict__ Wp, const float* __restrict__ bp,
                 const float* __restrict__ ctx)
{
    extern __shared__ __align__(16) float sh[];
    float* os = sh;                  // T*256
    float* S  = sh + T * 256;        // 2*T*128 partials, then logits in S[t*128]
    float* av = S + 2 * T * 128;     // T
    __shared__ float mv, sv;

    const int word = blockIdx.x, tid = threadIdx.x;
    const int c = tid & 127, kh = tid >> 7;

    const float4* src4 = (const float4*)(g_out + (size_t)word * T * 256);
    float4* os4 = (float4*)os;
    for (int i = tid; i < T * 64; i += 256) os4[i] = src4[i];

    ull w2[64];
    loadW<32>(w2, Wp + (size_t)c * 256 + kh * 128);
    __syncthreads();

    float* Sp = S + kh * T * 128 + c;
#pragma unroll 2
    for (int t = 0; t < T; t++) Sp[t * 128] = dotT<32>(w2, os + t * 256 + kh * 128);
    __syncthreads();

    for (int i = tid; i < T * 128; i += 256) {
        int cc = i & 127;
        float v = S[i] + S[T * 128 + i];
        S[i] = tanhf(v + bp[cc]) * ctx[cc];
    }
    for (int lo = 6; lo >= 0; lo--) {
        __syncthreads();
        int off = 1 << lo;
        for (int i = tid; i < T * off; i += 256) {
            int t = i >> lo, u = i & (off - 1);
            S[t * 128 + u] += S[t * 128 + u + off];
        }
    }
    __syncthreads();
    if (tid == 0) { float m = -1e30f; for (int t = 0; t < T; t++) m = fmaxf(m, S[t * 128]); mv = m; }
    __syncthreads();
    if (tid < T) av[tid] = expf(S[tid * 128] - mv);
    __syncthreads();
    if (tid == 0) { float s = 0.f; for (int t = 0; t < T; t++) s += av[t]; sv = 1.f / s; }
    __syncthreads();
    float acc = 0.f;
#pragma unroll 4
    for (int t = 0; t < T; t++) acc += av[t] * os[t * 256 + tid];
    g_words[(size_t)word * 256 + tid] = acc * sv;
}

// ---------------- K7: output head + writeback ----------------
__global__ __launch_bounds__(256, 1)
void final_kernel(const float* __restrict__ Wout, const float* __restrict__ bout,
                  float* __restrict__ out, int out_size)
{
    const int b = blockIdx.x, tid = threadIdx.x;
    const float* msg = g_words + (size_t)b * 256;
    const bool writeOut = (out_size != 32768);
    const bool writeMsg = (out_size >= 32768);
    const int msgOff = (out_size > 32768) ? 1024 : 0;
    if (writeMsg) out[msgOff + b * 256 + tid] = msg[tid];
    if (writeOut && tid < 8) {
        float acc = bout[tid];
        const float* wr = Wout + tid * 256;
        for (int kk = 0; kk < 256; kk++) acc += msg[kk] * wr[kk];
        out[b * 8 + tid] = acc;
    }
}

extern "C" void kernel_launch(void* const* d_in, const int* in_sizes, int n_in,
                              void* d_out, int out_size)
{
    const int*   chars  = (const int*)d_in[0];
    const int*   lens   = (const int*)d_in[1];
    const float* emb    = (const float*)d_in[2];
    const float* cWih_f = (const float*)d_in[3];
    const float* cWhh_f = (const float*)d_in[4];
    const float* cbih_f = (const float*)d_in[5];
    const float* cbhh_f = (const float*)d_in[6];
    const float* cWih_b = (const float*)d_in[7];
    const float* cWhh_b = (const float*)d_in[8];
    const float* cbih_b = (const float*)d_in[9];
    const float* cbhh_b = (const float*)d_in[10];
    const float* mWih_f = (const float*)d_in[11];
    const float* mWhh_f = (const float*)d_in[12];
    const float* mbih_f = (const float*)d_in[13];
    const float* mbhh_f = (const float*)d_in[14];
    const float* mWih_b = (const float*)d_in[15];
    const float* mWhh_b = (const float*)d_in[16];
    const float* mbih_b = (const float*)d_in[17];
    const float* mbhh_b = (const float*)d_in[18];
    const float* wWp    = (const float*)d_in[19];
    const float* wbp    = (const float*)d_in[20];
    const float* wctx   = (const float*)d_in[21];
    const float* pWp    = (const float*)d_in[22];
    const float* pbp    = (const float*)d_in[23];
    const float* pctx   = (const float*)d_in[24];
    const float* Wout   = (const float*)d_in[25];
    const float* bout   = (const float*)d_in[26];

    const int smXC  = (96 * 64 + 16 * 768 + 384) * 4;                     // 75264 B
    const int smK   = (16 * 256 + 16 * 512 + 64) * 4;                     // 49408 B
    const int smG16 = (16 * 128 + 384 * 17 + 128 * 17 + 16 * 768 + 384) * 4;  // 93696 B
    const int smG4  = (4 * 128 + 384 * 5 + 128 * 5 + 4 * 768 + 384) * 4;      // 26112 B
    const int smA48 = (48 * 256 + 2 * 48 * 128 + 48) * 4;                 // 98496 B
    const int smA64 = (64 * 256 + 2 * 64 * 128 + 64) * 4;                 // 131328 B

    cudaFuncSetAttribute(xg_char_kernel,  cudaFuncAttributeMaxDynamicSharedMemorySize, smXC);
    cudaFuncSetAttribute(xg_k256_kernel,  cudaFuncAttributeMaxDynamicSharedMemorySize, smK);
    cudaFuncSetAttribute(gru_kernel<16>,  cudaFuncAttributeMaxDynamicSharedMemorySize, smG16);
    cudaFuncSetAttribute(gru_kernel<4>,   cudaFuncAttributeMaxDynamicSharedMemorySize, smG4);
    cudaFuncSetAttribute(attn_kernel<48>, cudaFuncAttributeMaxDynamicSharedMemorySize, smA48);
    cudaFuncSetAttribute(attn_kernel<64>, cudaFuncAttributeMaxDynamicSharedMemorySize, smA64);

    // char level
    xg_char_kernel<<<dim3(2, 4096), 384, smXC>>>(chars, emb, cWih_f, cWih_b, cbih_f, cbih_b);
    gru_kernel<16><<<dim3(2, 512), 768, smG16>>>(cWhh_f, cWhh_b, cbhh_f, cbhh_b, lens, NSEQ_C, T_CH);
    attn_kernel<48><<<NSEQ_C, 256, smA48>>>(wWp, wbp, wctx);
    // message level
    xg_k256_kernel<<<dim3(12, 512), 256, smK>>>(mWih_f, mWih_b, mbih_f, mbih_b);
    gru_kernel<4><<<dim3(2, 32), 768, smG4>>>(mWhh_f, mWhh_b, mbhh_f, mbhh_b, nullptr, 128, 64);
    attn_kernel<64><<<128, 256, smA64>>>(pWp, pbp, pctx);
    // head + writeback
    final_kernel<<<128, 256>>>(Wout, bout, (float*)d_out, out_size);
}

// round 17
// speedup vs baseline: 1.0030x; 1.0030x over previous
#include <cuda_runtime.h>
#include <math.h>

typedef unsigned long long ull;

// Shapes
#define NSEQ_C 8192            // B*W
#define T_CH   48              // chars per word
#define M_C    (NSEQ_C*T_CH)   // 393216 char rows
#define M_M    8192            // msg-level rows (B*W)

// ---------------- static device scratch (no allocations allowed) ----------------
__device__ float g_xg[301989888ull];        // [2][M][384] gate preacts
__device__ float g_out[100663296ull];       // [M][256] BiGRU outputs
__device__ float g_words[2097152ull];       // [8192][256] pooled word vectors / messages

// ---------------- helpers ----------------
__device__ __forceinline__ void ffma2(ull &d, ull a, ull b) {
    asm("fma.rn.f32x2 %0, %1, %2, %0;" : "+l"(d) : "l"(a), "l"(b));
}
__device__ __forceinline__ float f2sum(ull v) {
    unsigned lo, hi;
    asm("mov.b64 {%0,%1}, %2;" : "=r"(lo), "=r"(hi) : "l"(v));
    return __uint_as_float(lo) + __uint_as_float(hi);
}
__device__ __forceinline__ float sigmoidf_(float x) { return 1.0f / (1.0f + expf(-x)); }

// Load NU*4 floats of a weight row into packed-f32x2 registers (16B loads).
template <int NU>
__device__ __forceinline__ void loadW(ull* w2, const float* __restrict__ W) {
    const ulonglong2* wr = (const ulonglong2*)W;
#pragma unroll
    for (int j = 0; j < NU; j++) { ulonglong2 v = wr[j]; w2[2 * j] = v.x; w2[2 * j + 1] = v.y; }
}

// Single dot over NU*4 floats from shared (LDS.128), 4 independent chains.
template <int NU>
__device__ __forceinline__ float dotT(const ull* w2, const float* xp) {
    const ulonglong2* xr = (const ulonglong2*)xp;
    ull a0 = 0, a1 = 0, a2 = 0, a3 = 0;
#pragma unroll
    for (int j = 0; j < NU; j += 2) {
        ulonglong2 v0 = xr[j];
        ulonglong2 v1 = xr[j + 1];
        ffma2(a0, w2[2 * j],     v0.x);
        ffma2(a1, w2[2 * j + 1], v0.y);
        ffma2(a2, w2[2 * j + 2], v1.x);
        ffma2(a3, w2[2 * j + 3], v1.y);
    }
    return (f2sum(a0) + f2sum(a1)) + (f2sum(a2) + f2sum(a3));
}

// C simultaneous dots, two independent chains per column (used by xg_k256 only).
template <int C, int NU>
__device__ __forceinline__ void dotC(const ull* w, const float* xp, float* o) {
    const ulonglong2* xr = (const ulonglong2*)xp;
    ull ax[C], ay[C];
#pragma unroll
    for (int c = 0; c < C; c++) { ax[c] = 0; ay[c] = 0; }
#pragma unroll
    for (int j = 0; j < NU; j++) {
        ulonglong2 v = xr[j];
#pragma unroll
        for (int c = 0; c < C; c++) {
            ffma2(ax[c], w[c * 2 * NU + 2 * j],     v.x);
            ffma2(ay[c], w[c * 2 * NU + 2 * j + 1], v.y);
        }
    }
#pragma unroll
    for (int c = 0; c < C; c++) o[c] = f2sum(ax[c]) + f2sum(ay[c]);
}

// ---------------- K1: char input gates, fused embedding gather (K=64) — R10 exact ----------------
// 256 threads, 1 column/thread, full K in 64 regs -> 2 blocks/SM (16 warps).
__global__ __launch_bounds__(256, 2)
void xg_char_kernel(const int* __restrict__ chars, const float* __restrict__ emb,
                    const float* __restrict__ WihF, const float* __restrict__ WihB,
                    const float* __restrict__ biF,  const float* __restrict__ biB)
{
    const int RB = 96;
    __shared__ __align__(16) float xs[RB][64];
    const int m0  = blockIdx.y * RB;
    const int tid = threadIdx.x;
    const int gcol = blockIdx.x * 256 + tid;      // 0..767
    const int dir  = gcol >= 384;
    const int row  = gcol - dir * 384;

    ull w2[32];
    loadW<16>(w2, (dir ? WihB : WihF) + (size_t)row * 64);
    const float bias = (dir ? biB : biF)[row];

    float4* xs4 = (float4*)xs;
    const float4* emb4 = (const float4*)emb;
    for (int idx = tid; idx < RB * 16; idx += 256) {
        int r = idx >> 4, q = idx & 15;
        int ch = chars[m0 + r];
        xs4[idx] = emb4[(size_t)ch * 16 + q];
    }
    __syncthreads();

    float* outp = g_xg + (size_t)dir * M_C * 384 + (size_t)m0 * 384 + row;
#pragma unroll 2
    for (int r = 0; r < RB; r++) outp[(size_t)r * 384] = dotT<16>(w2, xs[r]) + bias;
}

// ---------------- K4: message input gates GEMM (K=256) — R14 measured-best ----------------
__global__ __launch_bounds__(256, 2)
void xg_k256_kernel(const float* __restrict__ WihF, const float* __restrict__ WihB,
                    const float* __restrict__ biF,  const float* __restrict__ biB)
{
    const int RB = 16;
    extern __shared__ __align__(16) float sh[];
    float* xs = sh;                 // [16][256]
    float* ps = xs + RB * 256;      // [16][8*64]
    float* sb = ps + RB * 512;      // [64]

    const int colg = blockIdx.x;    // 0..11
    const int m0   = blockIdx.y * RB;
    const int tid  = threadIdx.x;
    const int kq = tid >> 5, cl = tid & 31;

    ull w[2 * 16];
#pragma unroll
    for (int ci = 0; ci < 2; ci++) {
        int gcol = colg * 64 + cl + 32 * ci;
        int d = gcol >= 384, rw = gcol - d * 384;
        loadW<8>(w + ci * 16, (d ? WihB : WihF) + (size_t)rw * 256 + kq * 32);
    }
    if (tid < 64) {
        int gcol = colg * 64 + tid;
        int d = gcol >= 384, rw = gcol - d * 384;
        sb[tid] = (d ? biB : biF)[rw];
    }

    float4* xs4 = (float4*)xs;
    const float4* X4 = (const float4*)(g_words + (size_t)m0 * 256);
    for (int i = tid; i < RB * 64; i += 256) xs4[i] = X4[i];
    __syncthreads();

#pragma unroll 2
    for (int r = 0; r < RB; r++) {
        float o[2];
        dotC<2, 8>(w, xs + r * 256 + kq * 32, o);
        ps[r * 512 + kq * 64 + cl]      = o[0];
        ps[r * 512 + kq * 64 + cl + 32] = o[1];
    }
    __syncthreads();

#pragma unroll
    for (int p = 0; p < 4; p++) {
        int i = tid + p * 256;
        int r = i >> 6, col = i & 63;
        float v = sb[col];
#pragma unroll
        for (int q = 0; q < 8; q++) v += ps[r * 512 + q * 64 + col];
        int gcol = colg * 64 + col;
        int d = gcol >= 384, rw = gcol - d * 384;
        g_xg[(size_t)d * M_M * 384 + (size_t)(m0 + r) * 384 + rw] = v;
    }
}

// ---------------- K2/K5: persistent BiGRU recurrence — R10 exact ----------------
template <int NB>
__global__ __launch_bounds__(768, 1)
void gru_kernel(const float* __restrict__ WhF, const float* __restrict__ WhB,
                const float* __restrict__ bhF, const float* __restrict__ bhB,
                const int* __restrict__ lens, int nSeq, int T)
{
    extern __shared__ __align__(16) float sh[];
    float* hs   = sh;                         // [NB*128]
    float* HG   = hs + NB * 128;              // [384*(NB+1)]
    float* XN   = HG + 384 * (NB + 1);        // [128*(NB+1)]
    float* ps   = XN + 128 * (NB + 1);        // [NB*768]
    float* sbias= ps + NB * 768;              // [384]
    __shared__ int slen[NB];

    const int dir  = blockIdx.x;
    const int seq0 = blockIdx.y * NB;
    const int tid  = threadIdx.x;
    const int g    = tid % 384;
    const int kh   = tid / 384;               // warp-uniform (384 = 12 warps)

    const float* W = dir ? WhB : WhF;
    ull w2[32];
    loadW<16>(w2, W + (size_t)g * 128 + kh * 64);

    for (int i = tid; i < NB * 128; i += 768) hs[i] = 0.f;
    if (tid < 384) sbias[tid] = (dir ? bhB : bhF)[tid];
    if (tid < NB) slen[tid] = lens ? lens[seq0 + tid] : T;
    const float* xgD = g_xg + (size_t)dir * nSeq * T * 384;
    __syncthreads();

    const int k   = tid & 127;   // phase-2 mapping
    const int sub = tid >> 7;    // 0..5

    for (int t = 0; t < T; t++) {
        // phase 1a: half-dot partials for all b
#pragma unroll 1
        for (int b = 0; b < NB; b++)
            ps[b * 768 + tid] = dotT<16>(w2, hs + b * 128 + kh * 64);
        __syncthreads();
        // phase 1b: combine halves + bias + xg
        for (int i = tid; i < NB * 384; i += 768) {
            int b = i / 384, gg = i % 384;
            float hgv = ps[b * 768 + gg] + ps[b * 768 + gg + 384] + sbias[gg];
            int lb = slen[b];
            int it = dir ? ((t < lb) ? (lb - 1 - t) : t) : t;
            float xv = xgD[((size_t)(seq0 + b) * T + it) * 384 + gg];
            if (gg < 256) HG[gg * (NB + 1) + b] = xv + hgv;
            else { HG[gg * (NB + 1) + b] = hgv; XN[(gg - 256) * (NB + 1) + b] = xv; }
        }
        __syncthreads();
        // phase 2: gates + state update + output (6-way b split)
#pragma unroll 1
        for (int b = sub; b < NB; b += 6) {
            int lb = slen[b];
            bool valid = t < lb;
            float r = sigmoidf_(HG[k * (NB + 1) + b]);
            float z = sigmoidf_(HG[(k + 128) * (NB + 1) + b]);
            float n = tanhf(XN[k * (NB + 1) + b] + r * HG[(k + 256) * (NB + 1) + b]);
            float h = hs[b * 128 + k];
            float hnew = valid ? ((1.f - z) * n + z * h) : h;
            hs[b * 128 + k] = hnew;
            int ot = dir ? (valid ? (lb - 1 - t) : t) : t;
            size_t m = (size_t)(seq0 + b) * T + ot;
            g_out[m * 256 + (size_t)dir * 128 + k] = valid ? hnew : 0.f;
        }
        __syncthreads();
    }
}

// ---------------- K3/K6: attention pooling — R10 exact ----------------
template <int T>
__global__ __launch_bounds__(256, 1)
void attn_kernel(const float* __restrict__ Wp, const float* __restrict__ bp,
                 const float* __restrict__ ctx)
{
    extern __shared__ __align__(16) float sh[];
    float* os = sh;                  // T*256
    float* S  = sh + T * 256;        // 2*T*128 partials, then logits in S[t*128]
    float* av = S + 2 * T * 128;     // T
    __shared__ float mv, sv;

    const int word = blockIdx.x, tid = threadIdx.x;
    const int c = tid & 127, kh = tid >> 7;

    const float4* src4 = (const float4*)(g_out + (size_t)word * T * 256);
    float4* os4 = (float4*)os;
    for (int i = tid; i < T * 64; i += 256) os4[i] = src4[i];

    ull w2[64];
    loadW<32>(w2, Wp + (size_t)c * 256 + kh * 128);
    __syncthreads();

    float* Sp = S + kh * T * 128 + c;
#pragma unroll 2
    for (int t = 0; t < T; t++) Sp[t * 128] = dotT<32>(w2, os + t * 256 + kh * 128);
    __syncthreads();

    for (int i = tid; i < T * 128; i += 256) {
        int cc = i & 127;
        float v = S[i] + S[T * 128 + i];
        S[i] = tanhf(v + bp[cc]) * ctx[cc];
    }
    for (int lo = 6; lo >= 0; lo--) {
        __syncthreads();
        int off = 1 << lo;
        for (int i = tid; i < T * off; i += 256) {
            int t = i >> lo, u = i & (off - 1);
            S[t * 128 + u] += S[t * 128 + u + off];
        }
    }
    __syncthreads();
    if (tid == 0) { float m = -1e30f; for (int t = 0; t < T; t++) m = fmaxf(m, S[t * 128]); mv = m; }
    __syncthreads();
    if (tid < T) av[tid] = expf(S[tid * 128] - mv);
    __syncthreads();
    if (tid == 0) { float s = 0.f; for (int t = 0; t < T; t++) s += av[t]; sv = 1.f / s; }
    __syncthreads();
    float acc = 0.f;
#pragma unroll 4
    for (int t = 0; t < T; t++) acc += av[t] * os[t * 256 + tid];
    g_words[(size_t)word * 256 + tid] = acc * sv;
}

// ---------------- K7: output head + writeback — R10 exact ----------------
__global__ __launch_bounds__(256, 1)
void final_kernel(const float* __restrict__ Wout, const float* __restrict__ bout,
                  float* __restrict__ out, int out_size)
{
    const int b = blockIdx.x, tid = threadIdx.x;
    const float* msg = g_words + (size_t)b * 256;
    const bool writeOut = (out_size != 32768);
    const bool writeMsg = (out_size >= 32768);
    const int msgOff = (out_size > 32768) ? 1024 : 0;
    if (writeMsg) out[msgOff + b * 256 + tid] = msg[tid];
    if (writeOut && tid < 8) {
        float acc = bout[tid];
        const float* wr = Wout + tid * 256;
        for (int kk = 0; kk < 256; kk++) acc += msg[kk] * wr[kk];
        out[b * 8 + tid] = acc;
    }
}

extern "C" void kernel_launch(void* const* d_in, const int* in_sizes, int n_in,
                              void* d_out, int out_size)
{
    const int*   chars  = (const int*)d_in[0];
    const int*   lens   = (const int*)d_in[1];
    const float* emb    = (const float*)d_in[2];
    const float* cWih_f = (const float*)d_in[3];
    const float* cWhh_f = (const float*)d_in[4];
    const float* cbih_f = (const float*)d_in[5];
    const float* cbhh_f = (const float*)d_in[6];
    const float* cWih_b = (const float*)d_in[7];
    const float* cWhh_b = (const float*)d_in[8];
    const float* cbih_b = (const float*)d_in[9];
    const float* cbhh_b = (const float*)d_in[10];
    const float* mWih_f = (const float*)d_in[11];
    const float* mWhh_f = (const float*)d_in[12];
    const float* mbih_f = (const float*)d_in[13];
    const float* mbhh_f = (const float*)d_in[14];
    const float* mWih_b = (const float*)d_in[15];
    const float* mWhh_b = (const float*)d_in[16];
    const float* mbih_b = (const float*)d_in[17];
    const float* mbhh_b = (const float*)d_in[18];
    const float* wWp    = (const float*)d_in[19];
    const float* wbp    = (const float*)d_in[20];
    const float* wctx   = (const float*)d_in[21];
    const float* pWp    = (const float*)d_in[22];
    const float* pbp    = (const float*)d_in[23];
    const float* pctx   = (const float*)d_in[24];
    const float* Wout   = (const float*)d_in[25];
    const float* bout   = (const float*)d_in[26];

    const int smK   = (16 * 256 + 16 * 512 + 64) * 4;                         // 49408 B
    const int smG16 = (16 * 128 + 384 * 17 + 128 * 17 + 16 * 768 + 384) * 4;  // 93696 B
    const int smG4  = (4 * 128 + 384 * 5 + 128 * 5 + 4 * 768 + 384) * 4;      // 26112 B
    const int smA48 = (48 * 256 + 2 * 48 * 128 + 48) * 4;                     // 98496 B
    const int smA64 = (64 * 256 + 2 * 64 * 128 + 64) * 4;                     // 131328 B

    cudaFuncSetAttribute(xg_k256_kernel,  cudaFuncAttributeMaxDynamicSharedMemorySize, smK);
    cudaFuncSetAttribute(gru_kernel<16>,  cudaFuncAttributeMaxDynamicSharedMemorySize, smG16);
    cudaFuncSetAttribute(gru_kernel<4>,   cudaFuncAttributeMaxDynamicSharedMemorySize, smG4);
    cudaFuncSetAttribute(attn_kernel<48>, cudaFuncAttributeMaxDynamicSharedMemorySize, smA48);
    cudaFuncSetAttribute(attn_kernel<64>, cudaFuncAttributeMaxDynamicSharedMemorySize, smA64);

    // char level
    xg_char_kernel<<<dim3(3, 4096), 256>>>(chars, emb, cWih_f, cWih_b, cbih_f, cbih_b);
    gru_kernel<16><<<dim3(2, 512), 768, smG16>>>(cWhh_f, cWhh_b, cbhh_f, cbhh_b, lens, NSEQ_C, T_CH);
    attn_kernel<48><<<NSEQ_C, 256, smA48>>>(wWp, wbp, wctx);
    // message level
    xg_k256_kernel<<<dim3(12, 512), 256, smK>>>(mWih_f, mWih_b, mbih_f, mbih_b);
    gru_kernel<4><<<dim3(2, 32), 768, smG4>>>(mWhh_f, mWhh_b, mbhh_f, mbhh_b, nullptr, 128, 64);
    attn_kernel<64><<<128, 256, smA64>>>(pWp, pbp, pctx);
    // head + writeback
    final_kernel<<<128, 256>>>(Wout, bout, (float*)d_out, out_size);
}